// round 14
// baseline (speedup 1.0000x reference)
#include <cuda_runtime.h>
#include <cuda_bf16.h>
#include <cstdint>

// ---------------------------------------------------------------------------
// TCNet: B=128, NV=100, NQ=14, NA=10, V_DIM=2048, Q_DIM=1024, A_DIM=1024,
//        H_DIM=512, RANK=32, HD=16, G=2
//
// einsum 'rijkg,bnvi,bnqj,bnak->bvqag' : r and n are INDEPENDENT sums.
//   Tbar[i,j,k,g] = sum_r T[r,i,j,k,g]
//   out[b,v,q,a,g] = sum_{n,i,j,k} Tbar v_ q_ a_
//
// HMMA bf16x3 fp32 emulation. This round: PERSISTENT grouped GEMMs with
// atomic work-stealing (fixes the 24% wave-schedule loss), tq_tqa amortizes
// Tbar over 4 n per CTA, reduce_T merged into act_split.
// ---------------------------------------------------------------------------

#define Bb    128
#define NV    100
#define NQ    14
#define NA    10
#define RANK  32
#define G     2
#define QAG   (NQ*NA*G)   // 280
#define CPAD  288
#define PGRID 296          // persistent grid: 148 SMs x 2 CTAs

// ---------------- scratch (static device globals, zero-initialized) --------
__device__ __align__(256) __nv_bfloat16 g_v_hi [12800*2048], g_v_lo [12800*2048];
__device__ __align__(256) __nv_bfloat16 g_q_hi [1792*1024],  g_q_lo [1792*1024];
__device__ __align__(256) __nv_bfloat16 g_a_hi [1280*1024],  g_a_lo [1280*1024];
__device__ __align__(256) __nv_bfloat16 g_Wv_hi[512*2048],   g_Wv_lo[512*2048];
__device__ __align__(256) __nv_bfloat16 g_Wq_hi[512*1024],   g_Wq_lo[512*1024];
__device__ __align__(256) __nv_bfloat16 g_Wa_hi[512*1024],   g_Wa_lo[512*1024];
__device__ __align__(256) __nv_bfloat16 g_Wvr_hi[512*512],   g_Wvr_lo[512*512];
__device__ __align__(256) __nv_bfloat16 g_Wqr_hi[512*512],   g_Wqr_lo[512*512];
__device__ __align__(256) __nv_bfloat16 g_War_hi[512*512],   g_War_lo[512*512];
__device__ __align__(256) __nv_bfloat16 g_vt_hi[12800*512],  g_vt_lo[12800*512];
__device__ __align__(256) __nv_bfloat16 g_qt_hi[1792*512],   g_qt_lo[1792*512];
__device__ __align__(256) __nv_bfloat16 g_at_hi[1280*512],   g_at_lo[1280*512];
__device__ __align__(256) __nv_bfloat16 g_v2_hi[12832*512],  g_v2_lo[12832*512];
__device__ __align__(256) float g_q2[1792*512];
__device__ __align__(256) float g_a2[1280*512];
__device__ __align__(256) __nv_bfloat16 g_tqaT_hi[128*CPAD*512];
__device__ __align__(256) __nv_bfloat16 g_tqaT_lo[128*CPAD*512];
__device__ __align__(256) float g_Tbar[8192];
__device__ uint32_t g_ctr[4];

// ---------------- PTX helpers ----------------
__device__ __forceinline__ uint32_t smem_u32(const void* p) {
    uint32_t a;
    asm("{ .reg .u64 t; cvta.to.shared.u64 t, %1; cvt.u32.u64 %0, t; }"
        : "=r"(a) : "l"(p));
    return a;
}
__device__ __forceinline__ void mma_bf16(float* c, const uint32_t* a,
                                         const uint32_t* b) {
    asm volatile(
        "mma.sync.aligned.m16n8k16.row.col.f32.bf16.bf16.f32 "
        "{%0,%1,%2,%3}, {%4,%5,%6,%7}, {%8,%9}, {%0,%1,%2,%3};"
        : "+f"(c[0]), "+f"(c[1]), "+f"(c[2]), "+f"(c[3])
        : "r"(a[0]), "r"(a[1]), "r"(a[2]), "r"(a[3]), "r"(b[0]), "r"(b[1]));
}
__device__ __forceinline__ void ldsm4(uint32_t* r, uint32_t addr) {
    asm volatile("ldmatrix.sync.aligned.m8n8.x4.shared.b16 {%0,%1,%2,%3}, [%4];"
                 : "=r"(r[0]), "=r"(r[1]), "=r"(r[2]), "=r"(r[3]) : "r"(addr));
}
__device__ __forceinline__ void cp16(uint32_t dst, const void* src) {
    asm volatile("cp.async.cg.shared.global [%0], [%1], 16;"
                 :: "r"(dst), "l"(src));
}
__device__ __forceinline__ void cp_commit() {
    asm volatile("cp.async.commit_group;");
}
template<int N>
__device__ __forceinline__ void cp_wait() {
    asm volatile("cp.async.wait_group %0;" :: "n"(N));
}
__device__ __forceinline__ uint32_t swz_off(int row, int c) {
    return (uint32_t)(row * 64 + ((c ^ ((row >> 1) & 3)) << 4));
}

// ---------------------------------------------------------------------------
// counter reset (graph-deterministic: runs first every call)
// ---------------------------------------------------------------------------
__global__ void ctr_reset_kernel()
{
    if (threadIdx.x < 4) g_ctr[threadIdx.x] = 0;
}

// ---------------------------------------------------------------------------
// Splits: fp32 -> bf16 hi/lo, 8 elems/thread.
// ---------------------------------------------------------------------------
__device__ __forceinline__ void split8(const float* __restrict__ src,
                                       __nv_bfloat16* __restrict__ hi,
                                       __nv_bfloat16* __restrict__ lo, int i)
{
    float4 v0 = ((const float4*)src)[i * 2];
    float4 v1 = ((const float4*)src)[i * 2 + 1];
    float f[8] = {v0.x, v0.y, v0.z, v0.w, v1.x, v1.y, v1.z, v1.w};
    __nv_bfloat162 H[4], L[4];
    #pragma unroll
    for (int j = 0; j < 4; j++) {
        __nv_bfloat16 h0 = __float2bfloat16(f[j*2]);
        __nv_bfloat16 h1 = __float2bfloat16(f[j*2+1]);
        H[j] = {h0, h1};
        L[j] = {__float2bfloat16(f[j*2]   - __bfloat162float(h0)),
                __float2bfloat16(f[j*2+1] - __bfloat162float(h1))};
    }
    ((uint4*)hi)[i] = *(uint4*)H;
    ((uint4*)lo)[i] = *(uint4*)L;
}

// weights: Wv 131072, Wq 65536, Wa 65536, Wvr/Wqr/War 32768 each
#define RW_WQ   131072
#define RW_WA   196608
#define RW_WVR  262144
#define RW_WQR  294912
#define RW_WAR  327680
#define RW_END  360448
__global__ void w_split_kernel(const float* __restrict__ Wv,
                               const float* __restrict__ Wq,
                               const float* __restrict__ Wa,
                               const float* __restrict__ Wvr,
                               const float* __restrict__ Wqr,
                               const float* __restrict__ War)
{
    int gi = blockIdx.x * 256 + threadIdx.x;
    if (gi >= RW_END) return;
    if      (gi < RW_WQ)  split8(Wv,  g_Wv_hi,  g_Wv_lo,  gi);
    else if (gi < RW_WA)  split8(Wq,  g_Wq_hi,  g_Wq_lo,  gi - RW_WQ);
    else if (gi < RW_WVR) split8(Wa,  g_Wa_hi,  g_Wa_lo,  gi - RW_WA);
    else if (gi < RW_WQR) split8(Wvr, g_Wvr_hi, g_Wvr_lo, gi - RW_WVR);
    else if (gi < RW_WAR) split8(Wqr, g_Wqr_hi, g_Wqr_lo, gi - RW_WQR);
    else                  split8(War, g_War_hi, g_War_lo, gi - RW_WAR);
}

// activations + T-reduce: v 3276800, q 229376, a 163840, T 1024 (8 outs each)
#define RA_Q   3276800
#define RA_A   3506176
#define RA_T   3670016
#define RA_END 3671040
__global__ void act_split_kernel(const float* __restrict__ v,
                                 const float* __restrict__ q,
                                 const float* __restrict__ a,
                                 const float* __restrict__ T)
{
    int gi = blockIdx.x * 256 + threadIdx.x;
    if (gi >= RA_END) return;
    if      (gi < RA_Q) split8(v, g_v_hi, g_v_lo, gi);
    else if (gi < RA_A) split8(q, g_q_hi, g_q_lo, gi - RA_Q);
    else if (gi < RA_T) split8(a, g_a_hi, g_a_lo, gi - RA_A);
    else {
        int i = gi - RA_T;                 // 0..1023, 8 Tbar outputs each
        const float4* T4 = (const float4*)T;
        float4 s0 = {0,0,0,0}, s1 = {0,0,0,0};
        #pragma unroll
        for (int r = 0; r < RANK; r++) {
            float4 t0 = T4[(size_t)r * 2048 + i * 2];
            float4 t1 = T4[(size_t)r * 2048 + i * 2 + 1];
            s0.x += t0.x; s0.y += t0.y; s0.z += t0.z; s0.w += t0.w;
            s1.x += t1.x; s1.y += t1.y; s1.z += t1.z; s1.w += t1.w;
        }
        ((float4*)g_Tbar)[i * 2]     = s0;
        ((float4*)g_Tbar)[i * 2 + 1] = s1;
    }
}

// ---------------------------------------------------------------------------
// Persistent grouped HMMA bf16x3 GEMM with atomic work-stealing.
// Tiles: [0,400) v (cost 2 in S1), [400,456) q, [456,496) a.
// BM=128, BN=128, BK=32, 8 warps (32x64), 3-stage cp.async, 2 CTAs/SM.
// ---------------------------------------------------------------------------
#define NTILES 496
#define STAGE_SZ 32768
#define GEMM_SMEM (3 * STAGE_SZ)
#define OFF_AH 0
#define OFF_AL 8192
#define OFF_BH 16384
#define OFF_BL 24576
#define HN 512

template<int STAGE>
__global__ __launch_bounds__(256, 2)
void grouped_gemm(const float* __restrict__ bias_v,
                  const float* __restrict__ bias_q,
                  const float* __restrict__ bias_a)
{
    extern __shared__ char smem[];
    __shared__ int s_next;
    const uint32_t smb = smem_u32(smem);
    const int tid  = threadIdx.x;
    const int wid  = tid >> 5;
    const int lane = tid & 31;
    const int wm   = wid & 3;
    const int wn   = wid >> 2;

    const int a_r = (lane & 7) | (((lane >> 3) & 1) << 3);
    const int a_c = lane >> 4;
    const int b_r = (lane & 7) | ((lane >> 4) << 3);
    const int b_c = (lane >> 3) & 1;

    int id = blockIdx.x;
    while (id < NTILES) {
        // ---- problem dispatch ----
        const __nv_bfloat16 *Ahi, *Alo, *Bhi, *Blo;
        const float* bias;
        __nv_bfloat16 *Chi = nullptr, *Clo = nullptr;
        float* Cf = nullptr;
        int K, pid;
        bool outbf;

        if (STAGE == 1) {
            outbf = true;
            if (id < 400) {
                pid = id;       Ahi = g_v_hi; Alo = g_v_lo;
                Bhi = g_Wv_hi;  Blo = g_Wv_lo; K = 2048; bias = bias_v;
                Chi = g_vt_hi;  Clo = g_vt_lo;
            } else if (id < 456) {
                pid = id - 400; Ahi = g_q_hi; Alo = g_q_lo;
                Bhi = g_Wq_hi;  Blo = g_Wq_lo; K = 1024; bias = bias_q;
                Chi = g_qt_hi;  Clo = g_qt_lo;
            } else {
                pid = id - 456; Ahi = g_a_hi; Alo = g_a_lo;
                Bhi = g_Wa_hi;  Blo = g_Wa_lo; K = 1024; bias = bias_a;
                Chi = g_at_hi;  Clo = g_at_lo;
            }
        } else {
            K = 512;
            if (id < 400) {
                pid = id;       Ahi = g_vt_hi; Alo = g_vt_lo;
                Bhi = g_Wvr_hi; Blo = g_Wvr_lo; bias = bias_v;
                Chi = g_v2_hi;  Clo = g_v2_lo; outbf = true;
            } else if (id < 456) {
                pid = id - 400; Ahi = g_qt_hi; Alo = g_qt_lo;
                Bhi = g_Wqr_hi; Blo = g_Wqr_lo; bias = bias_q;
                Cf = g_q2; outbf = false;
            } else {
                pid = id - 456; Ahi = g_at_hi; Alo = g_at_lo;
                Bhi = g_War_hi; Blo = g_War_lo; bias = bias_a;
                Cf = g_a2; outbf = false;
            }
        }
        const int bm = (pid >> 2) * 128;
        const int bn = (pid & 3) * 128;
        const int nchunks = K >> 5;

        auto load_stage = [&](int c) {
            const uint32_t sb = smb + (uint32_t)(c % 3) * STAGE_SZ;
            const int k0 = c << 5;
            #pragma unroll
            for (int i = 0; i < 2; i++) {
                int idx = tid + i * 256;
                int row = idx >> 2;
                int cc  = idx & 3;
                uint32_t so = swz_off(row, cc);
                size_t gA = (size_t)(bm + row) * K + k0 + cc * 8;
                size_t gB = (size_t)(bn + row) * K + k0 + cc * 8;
                cp16(sb + OFF_AH + so, Ahi + gA);
                cp16(sb + OFF_AL + so, Alo + gA);
                cp16(sb + OFF_BH + so, Bhi + gB);
                cp16(sb + OFF_BL + so, Blo + gB);
            }
        };

        float acc[2][8][4];
        #pragma unroll
        for (int mt = 0; mt < 2; mt++)
            #pragma unroll
            for (int nt = 0; nt < 8; nt++)
                #pragma unroll
                for (int i = 0; i < 4; i++) acc[mt][nt][i] = 0.f;

        load_stage(0);
        cp_commit();
        load_stage(1);
        cp_commit();

        for (int c = 0; c < nchunks; c++) {
            cp_wait<1>();
            __syncthreads();

            if (c + 2 < nchunks) {
                load_stage(c + 2);
                cp_commit();
            } else {
                cp_commit();
            }

            const uint32_t sb = smb + (uint32_t)(c % 3) * STAGE_SZ;

            #pragma unroll
            for (int ks8 = 0; ks8 < 4; ks8 += 2) {
                uint32_t af[2][2][4];
                #pragma unroll
                for (int mt = 0; mt < 2; mt++) {
                    int row = wm * 32 + mt * 16 + a_r;
                    uint32_t so = swz_off(row, ks8 + a_c);
                    ldsm4(af[mt][0], sb + OFF_AH + so);
                    ldsm4(af[mt][1], sb + OFF_AL + so);
                }
                uint32_t bf[4][2][4];
                #pragma unroll
                for (int nq = 0; nq < 4; nq++) {
                    int row = wn * 64 + nq * 16 + b_r;
                    uint32_t so = swz_off(row, ks8 + b_c);
                    ldsm4(bf[nq][0], sb + OFF_BH + so);
                    ldsm4(bf[nq][1], sb + OFF_BL + so);
                }
                #pragma unroll
                for (int mt = 0; mt < 2; mt++)
                    #pragma unroll
                    for (int nq = 0; nq < 4; nq++)
                        #pragma unroll
                        for (int h = 0; h < 2; h++)
                            mma_bf16(acc[mt][nq*2+h], af[mt][0], &bf[nq][0][h*2]);
                #pragma unroll
                for (int mt = 0; mt < 2; mt++)
                    #pragma unroll
                    for (int nq = 0; nq < 4; nq++)
                        #pragma unroll
                        for (int h = 0; h < 2; h++)
                            mma_bf16(acc[mt][nq*2+h], af[mt][0], &bf[nq][1][h*2]);
                #pragma unroll
                for (int mt = 0; mt < 2; mt++)
                    #pragma unroll
                    for (int nq = 0; nq < 4; nq++)
                        #pragma unroll
                        for (int h = 0; h < 2; h++)
                            mma_bf16(acc[mt][nq*2+h], af[mt][1], &bf[nq][0][h*2]);
            }
        }

        // epilogue: bias + relu
        const int g = lane >> 2;
        const int t = lane & 3;
        #pragma unroll
        for (int mt = 0; mt < 2; mt++) {
            #pragma unroll
            for (int nt = 0; nt < 8; nt++) {
                int row0 = bm + wm * 32 + mt * 16 + g;
                int row1 = row0 + 8;
                int col  = bn + wn * 64 + nt * 8 + t * 2;
                float bs0 = __ldg(bias + col), bs1 = __ldg(bias + col + 1);
                float v00 = fmaxf(acc[mt][nt][0] + bs0, 0.f);
                float v01 = fmaxf(acc[mt][nt][1] + bs1, 0.f);
                float v10 = fmaxf(acc[mt][nt][2] + bs0, 0.f);
                float v11 = fmaxf(acc[mt][nt][3] + bs1, 0.f);
                if (outbf) {
                    __nv_bfloat16 h00 = __float2bfloat16(v00);
                    __nv_bfloat16 h01 = __float2bfloat16(v01);
                    __nv_bfloat16 h10 = __float2bfloat16(v10);
                    __nv_bfloat16 h11 = __float2bfloat16(v11);
                    __nv_bfloat162 H0 = {h00, h01}, H1 = {h10, h11};
                    __nv_bfloat162 L0 = {
                        __float2bfloat16(v00 - __bfloat162float(h00)),
                        __float2bfloat16(v01 - __bfloat162float(h01))};
                    __nv_bfloat162 L1 = {
                        __float2bfloat16(v10 - __bfloat162float(h10)),
                        __float2bfloat16(v11 - __bfloat162float(h11))};
                    *(__nv_bfloat162*)(Chi + (size_t)row0 * HN + col) = H0;
                    *(__nv_bfloat162*)(Clo + (size_t)row0 * HN + col) = L0;
                    *(__nv_bfloat162*)(Chi + (size_t)row1 * HN + col) = H1;
                    *(__nv_bfloat162*)(Clo + (size_t)row1 * HN + col) = L1;
                } else {
                    *(float2*)(Cf + (size_t)row0 * HN + col) = make_float2(v00, v01);
                    *(float2*)(Cf + (size_t)row1 * HN + col) = make_float2(v10, v11);
                }
            }
        }

        // grab next tile (also the smem-reuse barrier between tiles)
        if (tid == 0)
            s_next = PGRID + (int)atomicAdd(&g_ctr[STAGE - 1], 1u);
        __syncthreads();
        id = s_next;
    }
}

// ---------------------------------------------------------------------------
// K7: per (b, n0..n0+3):  Tq = Tbar x_j q_,  Tqa = Tq x_k a_
// Tbar loaded once per CTA, amortized over 4 n. Grid (8, 128).
// smem floats: sT 8192 | sQ 896 | sA 640 | sTq 7168 | sOut 4544 = 21440
// ---------------------------------------------------------------------------
#define TQ_SMEM (21440 * 4)

__global__ __launch_bounds__(256)
void tq_tqa_kernel()
{
    extern __shared__ float sm[];
    float* sT   = sm;                // 8192
    float* sQ   = sm + 8192;         // 896: [q][nl][j] = q*64+nl*16+j
    float* sA   = sm + 9088;         // 640: [a][nl][k]
    float* sTq  = sm + 9728;         // 7168
    float* sOut = sm + 16896;        // 4544: [ii][284]

    const int n0  = blockIdx.x * 4;
    const int b   = blockIdx.y;
    const int tid = threadIdx.x;

    for (int i = tid; i < 2048; i += 256)
        ((float4*)sT)[i] = ((const float4*)g_Tbar)[i];

    if (tid < 224) {
        int q  = tid >> 4;
        int nl = (tid >> 2) & 3;
        int j4 = (tid & 3) << 2;
        *(float4*)&sQ[q * 64 + nl * 16 + j4] =
            *(const float4*)(g_q2 + (size_t)(b * NQ + q) * 512 + (n0 + nl) * 16 + j4);
    }
    if (tid < 160) {
        int a  = tid >> 4;
        int nl = (tid >> 2) & 3;
        int k4 = (tid & 3) << 2;
        *(float4*)&sA[a * 64 + nl * 16 + k4] =
            *(const float4*)(g_a2 + (size_t)(b * NA + a) * 512 + (n0 + nl) * 16 + k4);
    }
    __syncthreads();

    for (int nl = 0; nl < 4; nl++) {
        // step A: Tq[q,i,k,g]
        {
            const int i_ = tid >> 4;
            const int k_ = tid & 15;
            float accx[14], accy[14];
            #pragma unroll
            for (int q = 0; q < 14; q++) { accx[q] = 0.f; accy[q] = 0.f; }
            #pragma unroll
            for (int j = 0; j < 16; j++) {
                float2 t2 = *(const float2*)&sT[(((i_ * 16 + j) * 16) + k_) * 2];
                #pragma unroll
                for (int q = 0; q < 14; q++) {
                    float qv = sQ[q * 64 + nl * 16 + j];
                    accx[q] = fmaf(t2.x, qv, accx[q]);
                    accy[q] = fmaf(t2.y, qv, accy[q]);
                }
            }
            #pragma unroll
            for (int q = 0; q < 14; q++)
                *(float2*)&sTq[((q * 16 + i_) * 16 + k_) * 2] =
                    make_float2(accx[q], accy[q]);
        }
        __syncthreads();

        // step B: contract with a_ -> sOut[ii][c]
        for (int t = tid; t < 2240; t += 256) {
            int ii  = t / 140;
            int rem = t - ii * 140;
            int q   = rem / 10;
            int a   = rem - q * 10;
            float sx = 0.f, sy = 0.f;
            #pragma unroll
            for (int k = 0; k < 16; k++) {
                float2 tq = *(const float2*)&sTq[((q * 16 + ii) * 16 + k) * 2];
                float  av = sA[a * 64 + nl * 16 + k];
                sx = fmaf(tq.x, av, sx);
                sy = fmaf(tq.y, av, sy);
            }
            sOut[ii * 284 + rem * 2]     = sx;
            sOut[ii * 284 + rem * 2 + 1] = sy;
        }
        __syncthreads();

        // write bf16 hi/lo transposed
        for (int idx = tid; idx < 560; idx += 256) {
            int c    = idx >> 1;
            int half = idx & 1;
            __nv_bfloat162 H[4], L[4];
            #pragma unroll
            for (int j = 0; j < 4; j++) {
                float v0 = sOut[(half * 8 + j * 2)     * 284 + c];
                float v1 = sOut[(half * 8 + j * 2 + 1) * 284 + c];
                __nv_bfloat16 h0 = __float2bfloat16(v0);
                __nv_bfloat16 h1 = __float2bfloat16(v1);
                H[j] = {h0, h1};
                L[j] = {__float2bfloat16(v0 - __bfloat162float(h0)),
                        __float2bfloat16(v1 - __bfloat162float(h1))};
            }
            size_t off = ((size_t)b * CPAD + c) * 512 + (n0 + nl) * 16 + half * 8;
            *(uint4*)(g_tqaT_hi + off) = *(uint4*)H;
            *(uint4*)(g_tqaT_lo + off) = *(uint4*)L;
        }
    }
}

// ---------------------------------------------------------------------------
// K8 (HMMA): out[b][v][c] = sum_k V2[b*100+v][k] * TQA_T[b][c][k]
// BM=128 (100 valid), BN=96, BK=32, 256 threads, 3-stage pipeline.
// ---------------------------------------------------------------------------
#define K8_STAGE 28672
#define K8_SMEM  (3 * K8_STAGE)
#define K8_BH    16384
#define K8_BL    22528

__global__ __launch_bounds__(256, 2)
void k8_gemm(float* __restrict__ out)
{
    extern __shared__ char smem[];
    const uint32_t smb = smem_u32(smem);
    const int tid  = threadIdx.x;
    const int wid  = tid >> 5;
    const int lane = tid & 31;
    const int wm   = wid & 3;
    const int wn   = wid >> 2;
    const int bn   = blockIdx.x * 96;
    const int b    = blockIdx.y;

    const __nv_bfloat16* Ahi = g_v2_hi + (size_t)b * 100 * 512;
    const __nv_bfloat16* Alo = g_v2_lo + (size_t)b * 100 * 512;
    const __nv_bfloat16* Bhi = g_tqaT_hi + ((size_t)b * CPAD + bn) * 512;
    const __nv_bfloat16* Blo = g_tqaT_lo + ((size_t)b * CPAD + bn) * 512;

    auto load_stage = [&](int c) {
        const uint32_t sb = smb + (uint32_t)(c % 3) * K8_STAGE;
        const int k0 = c << 5;
        #pragma unroll
        for (int i = 0; i < 2; i++) {
            int idx = tid + i * 256;
            int row = idx >> 2, cc = idx & 3;
            uint32_t so = swz_off(row, cc);
            size_t g = (size_t)row * 512 + k0 + cc * 8;
            cp16(sb + OFF_AH + so, Ahi + g);
            cp16(sb + OFF_AL + so, Alo + g);
        }
        {
            int row = tid >> 2, cc = tid & 3;
            uint32_t so = swz_off(row, cc);
            size_t g = (size_t)row * 512 + k0 + cc * 8;
            cp16(sb + K8_BH + so, Bhi + g);
            cp16(sb + K8_BL + so, Blo + g);
        }
        if (tid < 128) {
            int idx = tid + 256;
            int row = idx >> 2, cc = idx & 3;
            uint32_t so = swz_off(row, cc);
            size_t g = (size_t)row * 512 + k0 + cc * 8;
            cp16(sb + K8_BH + so, Bhi + g);
            cp16(sb + K8_BL + so, Blo + g);
        }
    };

    float acc[2][6][4];
    #pragma unroll
    for (int mt = 0; mt < 2; mt++)
        #pragma unroll
        for (int nt = 0; nt < 6; nt++)
            #pragma unroll
            for (int i = 0; i < 4; i++) acc[mt][nt][i] = 0.f;

    const int a_r = (lane & 7) | (((lane >> 3) & 1) << 3);
    const int a_c = lane >> 4;
    const int b_r = (lane & 7) | ((lane >> 4) << 3);
    const int b_c = (lane >> 3) & 1;

    load_stage(0);
    cp_commit();
    load_stage(1);
    cp_commit();

    for (int c = 0; c < 16; c++) {
        cp_wait<1>();
        __syncthreads();

        if (c + 2 < 16) {
            load_stage(c + 2);
            cp_commit();
        } else {
            cp_commit();
        }

        const uint32_t sb = smb + (uint32_t)(c % 3) * K8_STAGE;

        #pragma unroll
        for (int ks8 = 0; ks8 < 4; ks8 += 2) {
            uint32_t af[2][2][4];
            #pragma unroll
            for (int mt = 0; mt < 2; mt++) {
                int row = wm * 32 + mt * 16 + a_r;
                uint32_t so = swz_off(row, ks8 + a_c);
                ldsm4(af[mt][0], sb + OFF_AH + so);
                ldsm4(af[mt][1], sb + OFF_AL + so);
            }
            uint32_t bf[3][2][4];
            #pragma unroll
            for (int nq = 0; nq < 3; nq++) {
                int row = wn * 48 + nq * 16 + b_r;
                uint32_t so = swz_off(row, ks8 + b_c);
                ldsm4(bf[nq][0], sb + K8_BH + so);
                ldsm4(bf[nq][1], sb + K8_BL + so);
            }
            #pragma unroll
            for (int mt = 0; mt < 2; mt++)
                #pragma unroll
                for (int nq = 0; nq < 3; nq++)
                    #pragma unroll
                    for (int h = 0; h < 2; h++)
                        mma_bf16(acc[mt][nq*2+h], af[mt][0], &bf[nq][0][h*2]);
            #pragma unroll
            for (int mt = 0; mt < 2; mt++)
                #pragma unroll
                for (int nq = 0; nq < 3; nq++)
                    #pragma unroll
                    for (int h = 0; h < 2; h++)
                        mma_bf16(acc[mt][nq*2+h], af[mt][0], &bf[nq][1][h*2]);
            #pragma unroll
            for (int mt = 0; mt < 2; mt++)
                #pragma unroll
                for (int nq = 0; nq < 3; nq++)
                    #pragma unroll
                    for (int h = 0; h < 2; h++)
                        mma_bf16(acc[mt][nq*2+h], af[mt][1], &bf[nq][0][h*2]);
        }
    }

    const int g = lane >> 2;
    const int t = lane & 3;
    #pragma unroll
    for (int mt = 0; mt < 2; mt++) {
        #pragma unroll
        for (int nt = 0; nt < 6; nt++) {
            int v0 = wm * 32 + mt * 16 + g;
            int v1 = v0 + 8;
            int cg = bn + wn * 48 + nt * 8 + t * 2;
            if (cg < QAG) {
                if (v0 < NV)
                    *(float2*)(out + ((size_t)b * NV + v0) * QAG + cg) =
                        make_float2(acc[mt][nt][0], acc[mt][nt][1]);
                if (v1 < NV)
                    *(float2*)(out + ((size_t)b * NV + v1) * QAG + cg) =
                        make_float2(acc[mt][nt][2], acc[mt][nt][3]);
            }
        }
    }
}

// ---------------------------------------------------------------------------
extern "C" void kernel_launch(void* const* d_in, const int* in_sizes, int n_in,
                              void* d_out, int out_size)
{
    const float* v   = (const float*)d_in[0];
    const float* q   = (const float*)d_in[1];
    const float* a   = (const float*)d_in[2];
    const float* Wv  = (const float*)d_in[3];
    const float* bv  = (const float*)d_in[4];
    const float* Wq  = (const float*)d_in[5];
    const float* bq  = (const float*)d_in[6];
    const float* Wa  = (const float*)d_in[7];
    const float* ba  = (const float*)d_in[8];
    const float* Wvr = (const float*)d_in[9];
    const float* bvr = (const float*)d_in[10];
    const float* Wqr = (const float*)d_in[11];
    const float* bqr = (const float*)d_in[12];
    const float* War = (const float*)d_in[13];
    const float* bar = (const float*)d_in[14];
    const float* T   = (const float*)d_in[15];
    float* out       = (float*)d_out;

    cudaFuncSetAttribute(grouped_gemm<1>, cudaFuncAttributeMaxDynamicSharedMemorySize, GEMM_SMEM);
    cudaFuncSetAttribute(grouped_gemm<2>, cudaFuncAttributeMaxDynamicSharedMemorySize, GEMM_SMEM);
    cudaFuncSetAttribute(tq_tqa_kernel, cudaFuncAttributeMaxDynamicSharedMemorySize, TQ_SMEM);
    cudaFuncSetAttribute(k8_gemm, cudaFuncAttributeMaxDynamicSharedMemorySize, K8_SMEM);

    // 1: reset work-stealing counters
    ctr_reset_kernel<<<1, 32>>>();
    // 2: weight splits
    w_split_kernel<<<(RW_END + 255) / 256, 256>>>(Wv, Wq, Wa, Wvr, Wqr, War);
    // 3: activation splits + Tbar reduce (merged)
    act_split_kernel<<<(RA_END + 255) / 256, 256>>>(v, q, a, T);

    // 4: persistent grouped stage-1 [ncu-profiled position]
    grouped_gemm<1><<<PGRID, 256, GEMM_SMEM>>>(bv, bq, ba);

    // 5: persistent grouped stage-2
    grouped_gemm<2><<<PGRID, 256, GEMM_SMEM>>>(bvr, bqr, bar);

    // 6: Tucker core contraction -> TQA_T (bf16 hi/lo), 4 n per CTA
    tq_tqa_kernel<<<dim3(8, Bb), 256, TQ_SMEM>>>();

    // 7: batched final GEMM -> output
    k8_gemm<<<dim3(3, Bb), 256, K8_SMEM>>>(out);
}

// round 15
// speedup vs baseline: 1.3320x; 1.3320x over previous
#include <cuda_runtime.h>
#include <cuda_bf16.h>
#include <cstdint>

// ---------------------------------------------------------------------------
// TCNet: B=128, NV=100, NQ=14, NA=10, V_DIM=2048, Q_DIM=1024, A_DIM=1024,
//        H_DIM=512, RANK=32, HD=16, G=2
//
// einsum 'rijkg,bnvi,bnqj,bnak->bvqag' : r and n are INDEPENDENT sums.
//   Tbar[i,j,k,g] = sum_r T[r,i,j,k,g]
//   out[b,v,q,a,g] = sum_{n,i,j,k} Tbar v_ q_ a_
//
// HMMA bf16x3 fp32 emulation (hi*hi + hi*lo + lo*hi).
// This round: two-stream fork/join inside graph capture. The v chain
// (split_v -> S1v -> S2v) runs concurrently with the qa chain
// (split_qaT -> S1qa -> S2qa -> tq_tqa); qa CTAs fill the v GEMMs' tail
// waves. GEMM/tq/k8 kernels are the proven R13 versions.
// ---------------------------------------------------------------------------

#define Bb    128
#define NV    100
#define NQ    14
#define NA    10
#define RANK  32
#define G     2
#define QAG   (NQ*NA*G)   // 280
#define CPAD  288

// ---------------- scratch (static device globals, zero-initialized) --------
__device__ __align__(256) __nv_bfloat16 g_v_hi [12800*2048], g_v_lo [12800*2048];
__device__ __align__(256) __nv_bfloat16 g_q_hi [1792*1024],  g_q_lo [1792*1024];
__device__ __align__(256) __nv_bfloat16 g_a_hi [1280*1024],  g_a_lo [1280*1024];
__device__ __align__(256) __nv_bfloat16 g_Wv_hi[512*2048],   g_Wv_lo[512*2048];
__device__ __align__(256) __nv_bfloat16 g_Wq_hi[512*1024],   g_Wq_lo[512*1024];
__device__ __align__(256) __nv_bfloat16 g_Wa_hi[512*1024],   g_Wa_lo[512*1024];
__device__ __align__(256) __nv_bfloat16 g_Wvr_hi[512*512],   g_Wvr_lo[512*512];
__device__ __align__(256) __nv_bfloat16 g_Wqr_hi[512*512],   g_Wqr_lo[512*512];
__device__ __align__(256) __nv_bfloat16 g_War_hi[512*512],   g_War_lo[512*512];
__device__ __align__(256) __nv_bfloat16 g_vt_hi[12800*512],  g_vt_lo[12800*512];
__device__ __align__(256) __nv_bfloat16 g_qt_hi[1792*512],   g_qt_lo[1792*512];
__device__ __align__(256) __nv_bfloat16 g_at_hi[1280*512],   g_at_lo[1280*512];
__device__ __align__(256) __nv_bfloat16 g_v2_hi[12832*512],  g_v2_lo[12832*512];
__device__ __align__(256) float g_q2[1792*512];
__device__ __align__(256) float g_a2[1280*512];
__device__ __align__(256) __nv_bfloat16 g_tqaT_hi[128*CPAD*512];
__device__ __align__(256) __nv_bfloat16 g_tqaT_lo[128*CPAD*512];
__device__ __align__(256) float g_Tbar[8192];

// ---------------- PTX helpers ----------------
__device__ __forceinline__ uint32_t smem_u32(const void* p) {
    uint32_t a;
    asm("{ .reg .u64 t; cvta.to.shared.u64 t, %1; cvt.u32.u64 %0, t; }"
        : "=r"(a) : "l"(p));
    return a;
}
__device__ __forceinline__ void mma_bf16(float* c, const uint32_t* a,
                                         const uint32_t* b) {
    asm volatile(
        "mma.sync.aligned.m16n8k16.row.col.f32.bf16.bf16.f32 "
        "{%0,%1,%2,%3}, {%4,%5,%6,%7}, {%8,%9}, {%0,%1,%2,%3};"
        : "+f"(c[0]), "+f"(c[1]), "+f"(c[2]), "+f"(c[3])
        : "r"(a[0]), "r"(a[1]), "r"(a[2]), "r"(a[3]), "r"(b[0]), "r"(b[1]));
}
__device__ __forceinline__ void ldsm4(uint32_t* r, uint32_t addr) {
    asm volatile("ldmatrix.sync.aligned.m8n8.x4.shared.b16 {%0,%1,%2,%3}, [%4];"
                 : "=r"(r[0]), "=r"(r[1]), "=r"(r[2]), "=r"(r[3]) : "r"(addr));
}
__device__ __forceinline__ void cp16(uint32_t dst, const void* src) {
    asm volatile("cp.async.cg.shared.global [%0], [%1], 16;"
                 :: "r"(dst), "l"(src));
}
__device__ __forceinline__ void cp_commit() {
    asm volatile("cp.async.commit_group;");
}
template<int N>
__device__ __forceinline__ void cp_wait() {
    asm volatile("cp.async.wait_group %0;" :: "n"(N));
}
__device__ __forceinline__ uint32_t swz_off(int row, int c) {
    return (uint32_t)(row * 64 + ((c ^ ((row >> 1) & 3)) << 4));
}

// ---------------------------------------------------------------------------
// Splits: fp32 -> bf16 hi/lo, 8 elems/thread.
// ---------------------------------------------------------------------------
__device__ __forceinline__ void split8(const float* __restrict__ src,
                                       __nv_bfloat16* __restrict__ hi,
                                       __nv_bfloat16* __restrict__ lo, int i)
{
    float4 v0 = ((const float4*)src)[i * 2];
    float4 v1 = ((const float4*)src)[i * 2 + 1];
    float f[8] = {v0.x, v0.y, v0.z, v0.w, v1.x, v1.y, v1.z, v1.w};
    __nv_bfloat162 H[4], L[4];
    #pragma unroll
    for (int j = 0; j < 4; j++) {
        __nv_bfloat16 h0 = __float2bfloat16(f[j*2]);
        __nv_bfloat16 h1 = __float2bfloat16(f[j*2+1]);
        H[j] = {h0, h1};
        L[j] = {__float2bfloat16(f[j*2]   - __bfloat162float(h0)),
                __float2bfloat16(f[j*2+1] - __bfloat162float(h1))};
    }
    ((uint4*)hi)[i] = *(uint4*)H;
    ((uint4*)lo)[i] = *(uint4*)L;
}

// weights: Wv 131072, Wq 65536, Wa 65536, Wvr/Wqr/War 32768 each
#define RW_WQ   131072
#define RW_WA   196608
#define RW_WVR  262144
#define RW_WQR  294912
#define RW_WAR  327680
#define RW_END  360448
__global__ void w_split_kernel(const float* __restrict__ Wv,
                               const float* __restrict__ Wq,
                               const float* __restrict__ Wa,
                               const float* __restrict__ Wvr,
                               const float* __restrict__ Wqr,
                               const float* __restrict__ War)
{
    int gi = blockIdx.x * 256 + threadIdx.x;
    if (gi >= RW_END) return;
    if      (gi < RW_WQ)  split8(Wv,  g_Wv_hi,  g_Wv_lo,  gi);
    else if (gi < RW_WA)  split8(Wq,  g_Wq_hi,  g_Wq_lo,  gi - RW_WQ);
    else if (gi < RW_WVR) split8(Wa,  g_Wa_hi,  g_Wa_lo,  gi - RW_WA);
    else if (gi < RW_WQR) split8(Wvr, g_Wvr_hi, g_Wvr_lo, gi - RW_WVR);
    else if (gi < RW_WAR) split8(Wqr, g_Wqr_hi, g_Wqr_lo, gi - RW_WQR);
    else                  split8(War, g_War_hi, g_War_lo, gi - RW_WAR);
}

// v activations only
#define RV_END 3276800
__global__ void v_split_kernel(const float* __restrict__ v)
{
    int gi = blockIdx.x * 256 + threadIdx.x;
    if (gi >= RV_END) return;
    split8(v, g_v_hi, g_v_lo, gi);
}

// q, a activations + Tbar reduce: q 229376, a 163840, T 1024
#define RQ_A   229376
#define RQ_T   393216
#define RQ_END 394240
__global__ void qaT_split_kernel(const float* __restrict__ q,
                                 const float* __restrict__ a,
                                 const float* __restrict__ T)
{
    int gi = blockIdx.x * 256 + threadIdx.x;
    if (gi >= RQ_END) return;
    if      (gi < RQ_A) split8(q, g_q_hi, g_q_lo, gi);
    else if (gi < RQ_T) split8(a, g_a_hi, g_a_lo, gi - RQ_A);
    else {
        int i = gi - RQ_T;                 // 0..1023, 8 Tbar outputs each
        const float4* T4 = (const float4*)T;
        float4 s0 = {0,0,0,0}, s1 = {0,0,0,0};
        #pragma unroll
        for (int r = 0; r < RANK; r++) {
            float4 t0 = T4[(size_t)r * 2048 + i * 2];
            float4 t1 = T4[(size_t)r * 2048 + i * 2 + 1];
            s0.x += t0.x; s0.y += t0.y; s0.z += t0.z; s0.w += t0.w;
            s1.x += t1.x; s1.y += t1.y; s1.z += t1.z; s1.w += t1.w;
        }
        ((float4*)g_Tbar)[i * 2]     = s0;
        ((float4*)g_Tbar)[i * 2 + 1] = s1;
    }
}

// ---------------------------------------------------------------------------
// Grouped HMMA bf16x3 GEMM (R13 mainloop). Tile id = blockIdx.x + id0.
// ids: [0,400) v tiles, [400,456) q, [456,496) a.
// BM=128, BN=128, BK=32, 8 warps (32x64), 3-stage cp.async, 2 CTAs/SM.
// ---------------------------------------------------------------------------
#define STAGE_SZ 32768
#define GEMM_SMEM (3 * STAGE_SZ)
#define OFF_AH 0
#define OFF_AL 8192
#define OFF_BH 16384
#define OFF_BL 24576
#define HN 512

template<int STAGE>
__global__ __launch_bounds__(256, 2)
void grouped_gemm(const float* __restrict__ bias_v,
                  const float* __restrict__ bias_q,
                  const float* __restrict__ bias_a,
                  int id0)
{
    extern __shared__ char smem[];
    const uint32_t smb = smem_u32(smem);
    const int tid  = threadIdx.x;
    const int wid  = tid >> 5;
    const int lane = tid & 31;
    const int wm   = wid & 3;
    const int wn   = wid >> 2;
    const int id   = blockIdx.x + id0;

    const __nv_bfloat16 *Ahi, *Alo, *Bhi, *Blo;
    const float* bias;
    __nv_bfloat16 *Chi = nullptr, *Clo = nullptr;
    float* Cf = nullptr;
    int K, pid;
    bool outbf;

    if (STAGE == 1) {
        outbf = true;
        if (id < 400) {
            pid = id;       Ahi = g_v_hi; Alo = g_v_lo;
            Bhi = g_Wv_hi;  Blo = g_Wv_lo; K = 2048; bias = bias_v;
            Chi = g_vt_hi;  Clo = g_vt_lo;
        } else if (id < 456) {
            pid = id - 400; Ahi = g_q_hi; Alo = g_q_lo;
            Bhi = g_Wq_hi;  Blo = g_Wq_lo; K = 1024; bias = bias_q;
            Chi = g_qt_hi;  Clo = g_qt_lo;
        } else {
            pid = id - 456; Ahi = g_a_hi; Alo = g_a_lo;
            Bhi = g_Wa_hi;  Blo = g_Wa_lo; K = 1024; bias = bias_a;
            Chi = g_at_hi;  Clo = g_at_lo;
        }
    } else {
        K = 512;
        if (id < 400) {
            pid = id;       Ahi = g_vt_hi; Alo = g_vt_lo;
            Bhi = g_Wvr_hi; Blo = g_Wvr_lo; bias = bias_v;
            Chi = g_v2_hi;  Clo = g_v2_lo; outbf = true;
        } else if (id < 456) {
            pid = id - 400; Ahi = g_qt_hi; Alo = g_qt_lo;
            Bhi = g_Wqr_hi; Blo = g_Wqr_lo; bias = bias_q;
            Cf = g_q2; outbf = false;
        } else {
            pid = id - 456; Ahi = g_at_hi; Alo = g_at_lo;
            Bhi = g_War_hi; Blo = g_War_lo; bias = bias_a;
            Cf = g_a2; outbf = false;
        }
    }
    const int bm = (pid >> 2) * 128;
    const int bn = (pid & 3) * 128;
    const int nchunks = K >> 5;

    auto load_stage = [&](int c) {
        const uint32_t sb = smb + (uint32_t)(c % 3) * STAGE_SZ;
        const int k0 = c << 5;
        #pragma unroll
        for (int i = 0; i < 2; i++) {
            int idx = tid + i * 256;
            int row = idx >> 2;
            int cc  = idx & 3;
            uint32_t so = swz_off(row, cc);
            size_t gA = (size_t)(bm + row) * K + k0 + cc * 8;
            size_t gB = (size_t)(bn + row) * K + k0 + cc * 8;
            cp16(sb + OFF_AH + so, Ahi + gA);
            cp16(sb + OFF_AL + so, Alo + gA);
            cp16(sb + OFF_BH + so, Bhi + gB);
            cp16(sb + OFF_BL + so, Blo + gB);
        }
    };

    float acc[2][8][4];
    #pragma unroll
    for (int mt = 0; mt < 2; mt++)
        #pragma unroll
        for (int nt = 0; nt < 8; nt++)
            #pragma unroll
            for (int i = 0; i < 4; i++) acc[mt][nt][i] = 0.f;

    const int a_r = (lane & 7) | (((lane >> 3) & 1) << 3);
    const int a_c = lane >> 4;
    const int b_r = (lane & 7) | ((lane >> 4) << 3);
    const int b_c = (lane >> 3) & 1;

    load_stage(0);
    cp_commit();
    load_stage(1);
    cp_commit();

    for (int c = 0; c < nchunks; c++) {
        cp_wait<1>();
        __syncthreads();

        if (c + 2 < nchunks) {
            load_stage(c + 2);
            cp_commit();
        } else {
            cp_commit();
        }

        const uint32_t sb = smb + (uint32_t)(c % 3) * STAGE_SZ;

        #pragma unroll
        for (int ks8 = 0; ks8 < 4; ks8 += 2) {
            uint32_t af[2][2][4];
            #pragma unroll
            for (int mt = 0; mt < 2; mt++) {
                int row = wm * 32 + mt * 16 + a_r;
                uint32_t so = swz_off(row, ks8 + a_c);
                ldsm4(af[mt][0], sb + OFF_AH + so);
                ldsm4(af[mt][1], sb + OFF_AL + so);
            }
            uint32_t bf[4][2][4];
            #pragma unroll
            for (int nq = 0; nq < 4; nq++) {
                int row = wn * 64 + nq * 16 + b_r;
                uint32_t so = swz_off(row, ks8 + b_c);
                ldsm4(bf[nq][0], sb + OFF_BH + so);
                ldsm4(bf[nq][1], sb + OFF_BL + so);
            }
            #pragma unroll
            for (int mt = 0; mt < 2; mt++)
                #pragma unroll
                for (int nq = 0; nq < 4; nq++)
                    #pragma unroll
                    for (int h = 0; h < 2; h++)
                        mma_bf16(acc[mt][nq*2+h], af[mt][0], &bf[nq][0][h*2]);
            #pragma unroll
            for (int mt = 0; mt < 2; mt++)
                #pragma unroll
                for (int nq = 0; nq < 4; nq++)
                    #pragma unroll
                    for (int h = 0; h < 2; h++)
                        mma_bf16(acc[mt][nq*2+h], af[mt][0], &bf[nq][1][h*2]);
            #pragma unroll
            for (int mt = 0; mt < 2; mt++)
                #pragma unroll
                for (int nq = 0; nq < 4; nq++)
                    #pragma unroll
                    for (int h = 0; h < 2; h++)
                        mma_bf16(acc[mt][nq*2+h], af[mt][1], &bf[nq][0][h*2]);
        }
    }

    // epilogue: bias + relu
    const int g = lane >> 2;
    const int t = lane & 3;
    #pragma unroll
    for (int mt = 0; mt < 2; mt++) {
        #pragma unroll
        for (int nt = 0; nt < 8; nt++) {
            int row0 = bm + wm * 32 + mt * 16 + g;
            int row1 = row0 + 8;
            int col  = bn + wn * 64 + nt * 8 + t * 2;
            float bs0 = __ldg(bias + col), bs1 = __ldg(bias + col + 1);
            float v00 = fmaxf(acc[mt][nt][0] + bs0, 0.f);
            float v01 = fmaxf(acc[mt][nt][1] + bs1, 0.f);
            float v10 = fmaxf(acc[mt][nt][2] + bs0, 0.f);
            float v11 = fmaxf(acc[mt][nt][3] + bs1, 0.f);
            if (outbf) {
                __nv_bfloat16 h00 = __float2bfloat16(v00);
                __nv_bfloat16 h01 = __float2bfloat16(v01);
                __nv_bfloat16 h10 = __float2bfloat16(v10);
                __nv_bfloat16 h11 = __float2bfloat16(v11);
                __nv_bfloat162 H0 = {h00, h01}, H1 = {h10, h11};
                __nv_bfloat162 L0 = {
                    __float2bfloat16(v00 - __bfloat162float(h00)),
                    __float2bfloat16(v01 - __bfloat162float(h01))};
                __nv_bfloat162 L1 = {
                    __float2bfloat16(v10 - __bfloat162float(h10)),
                    __float2bfloat16(v11 - __bfloat162float(h11))};
                *(__nv_bfloat162*)(Chi + (size_t)row0 * HN + col) = H0;
                *(__nv_bfloat162*)(Clo + (size_t)row0 * HN + col) = L0;
                *(__nv_bfloat162*)(Chi + (size_t)row1 * HN + col) = H1;
                *(__nv_bfloat162*)(Clo + (size_t)row1 * HN + col) = L1;
            } else {
                *(float2*)(Cf + (size_t)row0 * HN + col) = make_float2(v00, v01);
                *(float2*)(Cf + (size_t)row1 * HN + col) = make_float2(v10, v11);
            }
        }
    }
}

// ---------------------------------------------------------------------------
// K7 (R13): per (b,n): Tq = Tbar x_j q_,  Tqa = Tq x_k a_
// Writes TQA transposed as bf16 hi/lo.
// ---------------------------------------------------------------------------
__global__ __launch_bounds__(256)
void tq_tqa_kernel()
{
    extern __shared__ float sm[];
    float* sT  = sm;               // 8192 (reused as sOut after step A)
    float* sQ  = sm + 8192;        // 224
    float* sA  = sm + 8416;        // 160
    float* sTq = sm + 8576;        // 7168

    const int n   = blockIdx.x;
    const int b   = blockIdx.y;
    const int tid = threadIdx.x;

    const float4* Tp = (const float4*)g_Tbar;
    for (int i = tid; i < 2048; i += 256) ((float4*)sT)[i] = Tp[i];

    if (tid < 56) {
        int q  = tid >> 2;
        int j4 = (tid & 3) << 2;
        *(float4*)&sQ[q * 16 + j4] =
            *(const float4*)(g_q2 + (size_t)(b * NQ + q) * 512 + n * 16 + j4);
    }
    if (tid >= 64 && tid < 104) {
        int t  = tid - 64;
        int a  = t >> 2;
        int k4 = (t & 3) << 2;
        *(float4*)&sA[a * 16 + k4] =
            *(const float4*)(g_a2 + (size_t)(b * NA + a) * 512 + n * 16 + k4);
    }
    __syncthreads();

    {
        const int i_ = tid >> 4;
        const int k_ = tid & 15;
        float accx[14], accy[14];
        #pragma unroll
        for (int q = 0; q < 14; q++) { accx[q] = 0.f; accy[q] = 0.f; }
        #pragma unroll
        for (int j = 0; j < 16; j++) {
            float2 t2 = *(const float2*)&sT[(((i_ * 16 + j) * 16) + k_) * 2];
            #pragma unroll
            for (int q = 0; q < 14; q++) {
                float qv = sQ[q * 16 + j];
                accx[q] = fmaf(t2.x, qv, accx[q]);
                accy[q] = fmaf(t2.y, qv, accy[q]);
            }
        }
        #pragma unroll
        for (int q = 0; q < 14; q++)
            *(float2*)&sTq[((q * 16 + i_) * 16 + k_) * 2] =
                make_float2(accx[q], accy[q]);
    }
    __syncthreads();

    float* sOut = sT;   // [16][284]
    for (int t = tid; t < 2240; t += 256) {
        int ii  = t / 140;
        int rem = t - ii * 140;
        int q   = rem / 10;
        int a   = rem - q * 10;
        float sx = 0.f, sy = 0.f;
        #pragma unroll
        for (int k = 0; k < 16; k++) {
            float2 tq = *(const float2*)&sTq[((q * 16 + ii) * 16 + k) * 2];
            float  av = sA[a * 16 + k];
            sx = fmaf(tq.x, av, sx);
            sy = fmaf(tq.y, av, sy);
        }
        sOut[ii * 284 + rem * 2]     = sx;
        sOut[ii * 284 + rem * 2 + 1] = sy;
    }
    __syncthreads();

    for (int idx = tid; idx < 560; idx += 256) {
        int c    = idx >> 1;
        int half = idx & 1;
        __nv_bfloat162 H[4], L[4];
        #pragma unroll
        for (int j = 0; j < 4; j++) {
            float v0 = sOut[(half * 8 + j * 2)     * 284 + c];
            float v1 = sOut[(half * 8 + j * 2 + 1) * 284 + c];
            __nv_bfloat16 h0 = __float2bfloat16(v0);
            __nv_bfloat16 h1 = __float2bfloat16(v1);
            H[j] = {h0, h1};
            L[j] = {__float2bfloat16(v0 - __bfloat162float(h0)),
                    __float2bfloat16(v1 - __bfloat162float(h1))};
        }
        size_t off = ((size_t)b * CPAD + c) * 512 + n * 16 + half * 8;
        *(uint4*)(g_tqaT_hi + off) = *(uint4*)H;
        *(uint4*)(g_tqaT_lo + off) = *(uint4*)L;
    }
}

// ---------------------------------------------------------------------------
// K8 (R13): out[b][v][c] = sum_k V2[b*100+v][k] * TQA_T[b][c][k]
// ---------------------------------------------------------------------------
#define K8_STAGE 28672
#define K8_SMEM  (3 * K8_STAGE)
#define K8_BH    16384
#define K8_BL    22528

__global__ __launch_bounds__(256, 2)
void k8_gemm(float* __restrict__ out)
{
    extern __shared__ char smem[];
    const uint32_t smb = smem_u32(smem);
    const int tid  = threadIdx.x;
    const int wid  = tid >> 5;
    const int lane = tid & 31;
    const int wm   = wid & 3;
    const int wn   = wid >> 2;
    const int bn   = blockIdx.x * 96;
    const int b    = blockIdx.y;

    const __nv_bfloat16* Ahi = g_v2_hi + (size_t)b * 100 * 512;
    const __nv_bfloat16* Alo = g_v2_lo + (size_t)b * 100 * 512;
    const __nv_bfloat16* Bhi = g_tqaT_hi + ((size_t)b * CPAD + bn) * 512;
    const __nv_bfloat16* Blo = g_tqaT_lo + ((size_t)b * CPAD + bn) * 512;

    auto load_stage = [&](int c) {
        const uint32_t sb = smb + (uint32_t)(c % 3) * K8_STAGE;
        const int k0 = c << 5;
        #pragma unroll
        for (int i = 0; i < 2; i++) {
            int idx = tid + i * 256;
            int row = idx >> 2, cc = idx & 3;
            uint32_t so = swz_off(row, cc);
            size_t g = (size_t)row * 512 + k0 + cc * 8;
            cp16(sb + OFF_AH + so, Ahi + g);
            cp16(sb + OFF_AL + so, Alo + g);
        }
        {
            int row = tid >> 2, cc = tid & 3;
            uint32_t so = swz_off(row, cc);
            size_t g = (size_t)row * 512 + k0 + cc * 8;
            cp16(sb + K8_BH + so, Bhi + g);
            cp16(sb + K8_BL + so, Blo + g);
        }
        if (tid < 128) {
            int idx = tid + 256;
            int row = idx >> 2, cc = idx & 3;
            uint32_t so = swz_off(row, cc);
            size_t g = (size_t)row * 512 + k0 + cc * 8;
            cp16(sb + K8_BH + so, Bhi + g);
            cp16(sb + K8_BL + so, Blo + g);
        }
    };

    float acc[2][6][4];
    #pragma unroll
    for (int mt = 0; mt < 2; mt++)
        #pragma unroll
        for (int nt = 0; nt < 6; nt++)
            #pragma unroll
            for (int i = 0; i < 4; i++) acc[mt][nt][i] = 0.f;

    const int a_r = (lane & 7) | (((lane >> 3) & 1) << 3);
    const int a_c = lane >> 4;
    const int b_r = (lane & 7) | ((lane >> 4) << 3);
    const int b_c = (lane >> 3) & 1;

    load_stage(0);
    cp_commit();
    load_stage(1);
    cp_commit();

    for (int c = 0; c < 16; c++) {
        cp_wait<1>();
        __syncthreads();

        if (c + 2 < 16) {
            load_stage(c + 2);
            cp_commit();
        } else {
            cp_commit();
        }

        const uint32_t sb = smb + (uint32_t)(c % 3) * K8_STAGE;

        #pragma unroll
        for (int ks8 = 0; ks8 < 4; ks8 += 2) {
            uint32_t af[2][2][4];
            #pragma unroll
            for (int mt = 0; mt < 2; mt++) {
                int row = wm * 32 + mt * 16 + a_r;
                uint32_t so = swz_off(row, ks8 + a_c);
                ldsm4(af[mt][0], sb + OFF_AH + so);
                ldsm4(af[mt][1], sb + OFF_AL + so);
            }
            uint32_t bf[3][2][4];
            #pragma unroll
            for (int nq = 0; nq < 3; nq++) {
                int row = wn * 48 + nq * 16 + b_r;
                uint32_t so = swz_off(row, ks8 + b_c);
                ldsm4(bf[nq][0], sb + K8_BH + so);
                ldsm4(bf[nq][1], sb + K8_BL + so);
            }
            #pragma unroll
            for (int mt = 0; mt < 2; mt++)
                #pragma unroll
                for (int nq = 0; nq < 3; nq++)
                    #pragma unroll
                    for (int h = 0; h < 2; h++)
                        mma_bf16(acc[mt][nq*2+h], af[mt][0], &bf[nq][0][h*2]);
            #pragma unroll
            for (int mt = 0; mt < 2; mt++)
                #pragma unroll
                for (int nq = 0; nq < 3; nq++)
                    #pragma unroll
                    for (int h = 0; h < 2; h++)
                        mma_bf16(acc[mt][nq*2+h], af[mt][0], &bf[nq][1][h*2]);
            #pragma unroll
            for (int mt = 0; mt < 2; mt++)
                #pragma unroll
                for (int nq = 0; nq < 3; nq++)
                    #pragma unroll
                    for (int h = 0; h < 2; h++)
                        mma_bf16(acc[mt][nq*2+h], af[mt][1], &bf[nq][0][h*2]);
        }
    }

    const int g = lane >> 2;
    const int t = lane & 3;
    #pragma unroll
    for (int mt = 0; mt < 2; mt++) {
        #pragma unroll
        for (int nt = 0; nt < 6; nt++) {
            int v0 = wm * 32 + mt * 16 + g;
            int v1 = v0 + 8;
            int cg = bn + wn * 48 + nt * 8 + t * 2;
            if (cg < QAG) {
                if (v0 < NV)
                    *(float2*)(out + ((size_t)b * NV + v0) * QAG + cg) =
                        make_float2(acc[mt][nt][0], acc[mt][nt][1]);
                if (v1 < NV)
                    *(float2*)(out + ((size_t)b * NV + v1) * QAG + cg) =
                        make_float2(acc[mt][nt][2], acc[mt][nt][3]);
            }
        }
    }
}

// ---------------------------------------------------------------------------
extern "C" void kernel_launch(void* const* d_in, const int* in_sizes, int n_in,
                              void* d_out, int out_size)
{
    const float* v   = (const float*)d_in[0];
    const float* q   = (const float*)d_in[1];
    const float* a   = (const float*)d_in[2];
    const float* Wv  = (const float*)d_in[3];
    const float* bv  = (const float*)d_in[4];
    const float* Wq  = (const float*)d_in[5];
    const float* bq  = (const float*)d_in[6];
    const float* Wa  = (const float*)d_in[7];
    const float* ba  = (const float*)d_in[8];
    const float* Wvr = (const float*)d_in[9];
    const float* bvr = (const float*)d_in[10];
    const float* Wqr = (const float*)d_in[11];
    const float* bqr = (const float*)d_in[12];
    const float* War = (const float*)d_in[13];
    const float* bar = (const float*)d_in[14];
    const float* T   = (const float*)d_in[15];
    float* out       = (float*)d_out;

    cudaFuncSetAttribute(grouped_gemm<1>, cudaFuncAttributeMaxDynamicSharedMemorySize, GEMM_SMEM);
    cudaFuncSetAttribute(grouped_gemm<2>, cudaFuncAttributeMaxDynamicSharedMemorySize, GEMM_SMEM);
    cudaFuncSetAttribute(tq_tqa_kernel, cudaFuncAttributeMaxDynamicSharedMemorySize, 62976);
    cudaFuncSetAttribute(k8_gemm, cudaFuncAttributeMaxDynamicSharedMemorySize, K8_SMEM);

    // side stream + fork/join events (host objects only; kernel_launch runs
    // just a couple of times: correctness + capture)
    cudaStream_t s1;
    cudaStreamCreateWithFlags(&s1, cudaStreamNonBlocking);
    cudaEvent_t evFork, evJoin;
    cudaEventCreateWithFlags(&evFork, cudaEventDisableTiming);
    cudaEventCreateWithFlags(&evJoin, cudaEventDisableTiming);

    // launch 1 (stream 0): weight splits (feeds both chains)
    w_split_kernel<<<(RW_END + 255) / 256, 256>>>(Wv, Wq, Wa, Wvr, Wqr, War);

    // fork
    cudaEventRecord(evFork, 0);
    cudaStreamWaitEvent(s1, evFork, 0);

    // ---- qa chain on s1 ----
    // launch 2: q/a splits + Tbar reduce
    qaT_split_kernel<<<(RQ_END + 255) / 256, 256, 0, s1>>>(q, a, T);
    // ---- v chain on stream 0 ----
    // launch 3: v split
    v_split_kernel<<<(RV_END + 255) / 256, 256>>>(v);
    // launch 4: stage-1 v GEMM (400 tiles) [ncu-profiled position]
    grouped_gemm<1><<<400, 256, GEMM_SMEM>>>(bv, bq, ba, 0);

    // qa chain continues on s1
    grouped_gemm<1><<<96, 256, GEMM_SMEM, s1>>>(bv, bq, ba, 400);
    grouped_gemm<2><<<96, 256, GEMM_SMEM, s1>>>(bvr, bqr, bar, 400);
    tq_tqa_kernel<<<dim3(RANK, Bb), 256, 62976, s1>>>();
    cudaEventRecord(evJoin, s1);

    // v chain continues on 0
    grouped_gemm<2><<<400, 256, GEMM_SMEM>>>(bvr, bqr, bar, 0);

    // join + final GEMM on 0
    cudaStreamWaitEvent(0, evJoin, 0);
    k8_gemm<<<dim3(3, Bb), 256, K8_SMEM>>>(out);

    cudaEventDestroy(evFork);
    cudaEventDestroy(evJoin);
    cudaStreamDestroy(s1);
}

// round 16
// speedup vs baseline: 1.3884x; 1.0424x over previous
#include <cuda_runtime.h>
#include <cuda_bf16.h>
#include <cstdint>

// ---------------------------------------------------------------------------
// TCNet: B=128, NV=100, NQ=14, NA=10, V_DIM=2048, Q_DIM=1024, A_DIM=1024,
//        H_DIM=512, RANK=32, HD=16, G=2
//
// einsum 'rijkg,bnvi,bnqj,bnak->bvqag' : r and n are INDEPENDENT sums.
//   Tbar[i,j,k,g] = sum_r T[r,i,j,k,g]
//   out[b,v,q,a,g] = sum_{n,i,j,k} Tbar v_ q_ a_
//
// HMMA bf16x3 fp32 emulation (hi*hi + hi*lo + lo*hi).
// This round: deeper multi-stream pipelining. v chain split into row-halves
// on two streams (split-h2 overlaps S1v-h1; S2v-h1 overlaps S1v-h2); k8 in
// b-halves so k8-h1 overlaps S2v-h2. w_split on its own stream at t=0.
// GEMM/tq/k8 kernels identical to R15.
// ---------------------------------------------------------------------------

#define Bb    128
#define NV    100
#define NQ    14
#define NA    10
#define RANK  32
#define G     2
#define QAG   (NQ*NA*G)   // 280
#define CPAD  288

// ---------------- scratch (static device globals, zero-initialized) --------
__device__ __align__(256) __nv_bfloat16 g_v_hi [12800*2048], g_v_lo [12800*2048];
__device__ __align__(256) __nv_bfloat16 g_q_hi [1792*1024],  g_q_lo [1792*1024];
__device__ __align__(256) __nv_bfloat16 g_a_hi [1280*1024],  g_a_lo [1280*1024];
__device__ __align__(256) __nv_bfloat16 g_Wv_hi[512*2048],   g_Wv_lo[512*2048];
__device__ __align__(256) __nv_bfloat16 g_Wq_hi[512*1024],   g_Wq_lo[512*1024];
__device__ __align__(256) __nv_bfloat16 g_Wa_hi[512*1024],   g_Wa_lo[512*1024];
__device__ __align__(256) __nv_bfloat16 g_Wvr_hi[512*512],   g_Wvr_lo[512*512];
__device__ __align__(256) __nv_bfloat16 g_Wqr_hi[512*512],   g_Wqr_lo[512*512];
__device__ __align__(256) __nv_bfloat16 g_War_hi[512*512],   g_War_lo[512*512];
__device__ __align__(256) __nv_bfloat16 g_vt_hi[12800*512],  g_vt_lo[12800*512];
__device__ __align__(256) __nv_bfloat16 g_qt_hi[1792*512],   g_qt_lo[1792*512];
__device__ __align__(256) __nv_bfloat16 g_at_hi[1280*512],   g_at_lo[1280*512];
__device__ __align__(256) __nv_bfloat16 g_v2_hi[12832*512],  g_v2_lo[12832*512];
__device__ __align__(256) float g_q2[1792*512];
__device__ __align__(256) float g_a2[1280*512];
__device__ __align__(256) __nv_bfloat16 g_tqaT_hi[128*CPAD*512];
__device__ __align__(256) __nv_bfloat16 g_tqaT_lo[128*CPAD*512];
__device__ __align__(256) float g_Tbar[8192];

// ---------------- PTX helpers ----------------
__device__ __forceinline__ uint32_t smem_u32(const void* p) {
    uint32_t a;
    asm("{ .reg .u64 t; cvta.to.shared.u64 t, %1; cvt.u32.u64 %0, t; }"
        : "=r"(a) : "l"(p));
    return a;
}
__device__ __forceinline__ void mma_bf16(float* c, const uint32_t* a,
                                         const uint32_t* b) {
    asm volatile(
        "mma.sync.aligned.m16n8k16.row.col.f32.bf16.bf16.f32 "
        "{%0,%1,%2,%3}, {%4,%5,%6,%7}, {%8,%9}, {%0,%1,%2,%3};"
        : "+f"(c[0]), "+f"(c[1]), "+f"(c[2]), "+f"(c[3])
        : "r"(a[0]), "r"(a[1]), "r"(a[2]), "r"(a[3]), "r"(b[0]), "r"(b[1]));
}
__device__ __forceinline__ void ldsm4(uint32_t* r, uint32_t addr) {
    asm volatile("ldmatrix.sync.aligned.m8n8.x4.shared.b16 {%0,%1,%2,%3}, [%4];"
                 : "=r"(r[0]), "=r"(r[1]), "=r"(r[2]), "=r"(r[3]) : "r"(addr));
}
__device__ __forceinline__ void cp16(uint32_t dst, const void* src) {
    asm volatile("cp.async.cg.shared.global [%0], [%1], 16;"
                 :: "r"(dst), "l"(src));
}
__device__ __forceinline__ void cp_commit() {
    asm volatile("cp.async.commit_group;");
}
template<int N>
__device__ __forceinline__ void cp_wait() {
    asm volatile("cp.async.wait_group %0;" :: "n"(N));
}
__device__ __forceinline__ uint32_t swz_off(int row, int c) {
    return (uint32_t)(row * 64 + ((c ^ ((row >> 1) & 3)) << 4));
}

// ---------------------------------------------------------------------------
// Splits: fp32 -> bf16 hi/lo, 8 elems/thread.
// ---------------------------------------------------------------------------
__device__ __forceinline__ void split8(const float* __restrict__ src,
                                       __nv_bfloat16* __restrict__ hi,
                                       __nv_bfloat16* __restrict__ lo, int i)
{
    float4 v0 = ((const float4*)src)[i * 2];
    float4 v1 = ((const float4*)src)[i * 2 + 1];
    float f[8] = {v0.x, v0.y, v0.z, v0.w, v1.x, v1.y, v1.z, v1.w};
    __nv_bfloat162 H[4], L[4];
    #pragma unroll
    for (int j = 0; j < 4; j++) {
        __nv_bfloat16 h0 = __float2bfloat16(f[j*2]);
        __nv_bfloat16 h1 = __float2bfloat16(f[j*2+1]);
        H[j] = {h0, h1};
        L[j] = {__float2bfloat16(f[j*2]   - __bfloat162float(h0)),
                __float2bfloat16(f[j*2+1] - __bfloat162float(h1))};
    }
    ((uint4*)hi)[i] = *(uint4*)H;
    ((uint4*)lo)[i] = *(uint4*)L;
}

// weights: Wv 131072, Wq 65536, Wa 65536, Wvr/Wqr/War 32768 each
#define RW_WQ   131072
#define RW_WA   196608
#define RW_WVR  262144
#define RW_WQR  294912
#define RW_WAR  327680
#define RW_END  360448
__global__ void w_split_kernel(const float* __restrict__ Wv,
                               const float* __restrict__ Wq,
                               const float* __restrict__ Wa,
                               const float* __restrict__ Wvr,
                               const float* __restrict__ Wqr,
                               const float* __restrict__ War)
{
    int gi = blockIdx.x * 256 + threadIdx.x;
    if (gi >= RW_END) return;
    if      (gi < RW_WQ)  split8(Wv,  g_Wv_hi,  g_Wv_lo,  gi);
    else if (gi < RW_WA)  split8(Wq,  g_Wq_hi,  g_Wq_lo,  gi - RW_WQ);
    else if (gi < RW_WVR) split8(Wa,  g_Wa_hi,  g_Wa_lo,  gi - RW_WA);
    else if (gi < RW_WQR) split8(Wvr, g_Wvr_hi, g_Wvr_lo, gi - RW_WVR);
    else if (gi < RW_WAR) split8(Wqr, g_Wqr_hi, g_Wqr_lo, gi - RW_WQR);
    else                  split8(War, g_War_hi, g_War_lo, gi - RW_WAR);
}

// v activations: half = rows 0..6399 or 6400..12799 (1638400 u8-slots each)
#define RV_HALF 1638400
__global__ void v_split_kernel(const float* __restrict__ v, int base)
{
    int gi = blockIdx.x * 256 + threadIdx.x;
    if (gi >= RV_HALF) return;
    split8(v, g_v_hi, g_v_lo, gi + base);
}

// q, a activations + Tbar reduce: q 229376, a 163840, T 1024
#define RQ_A   229376
#define RQ_T   393216
#define RQ_END 394240
__global__ void qaT_split_kernel(const float* __restrict__ q,
                                 const float* __restrict__ a,
                                 const float* __restrict__ T)
{
    int gi = blockIdx.x * 256 + threadIdx.x;
    if (gi >= RQ_END) return;
    if      (gi < RQ_A) split8(q, g_q_hi, g_q_lo, gi);
    else if (gi < RQ_T) split8(a, g_a_hi, g_a_lo, gi - RQ_A);
    else {
        int i = gi - RQ_T;
        const float4* T4 = (const float4*)T;
        float4 s0 = {0,0,0,0}, s1 = {0,0,0,0};
        #pragma unroll
        for (int r = 0; r < RANK; r++) {
            float4 t0 = T4[(size_t)r * 2048 + i * 2];
            float4 t1 = T4[(size_t)r * 2048 + i * 2 + 1];
            s0.x += t0.x; s0.y += t0.y; s0.z += t0.z; s0.w += t0.w;
            s1.x += t1.x; s1.y += t1.y; s1.z += t1.z; s1.w += t1.w;
        }
        ((float4*)g_Tbar)[i * 2]     = s0;
        ((float4*)g_Tbar)[i * 2 + 1] = s1;
    }
}

// ---------------------------------------------------------------------------
// Grouped HMMA bf16x3 GEMM (R13/R15 mainloop). Tile id = blockIdx.x + id0.
// ids: [0,400) v tiles, [400,456) q, [456,496) a.
// ---------------------------------------------------------------------------
#define STAGE_SZ 32768
#define GEMM_SMEM (3 * STAGE_SZ)
#define OFF_AH 0
#define OFF_AL 8192
#define OFF_BH 16384
#define OFF_BL 24576
#define HN 512

template<int STAGE>
__global__ __launch_bounds__(256, 2)
void grouped_gemm(const float* __restrict__ bias_v,
                  const float* __restrict__ bias_q,
                  const float* __restrict__ bias_a,
                  int id0)
{
    extern __shared__ char smem[];
    const uint32_t smb = smem_u32(smem);
    const int tid  = threadIdx.x;
    const int wid  = tid >> 5;
    const int lane = tid & 31;
    const int wm   = wid & 3;
    const int wn   = wid >> 2;
    const int id   = blockIdx.x + id0;

    const __nv_bfloat16 *Ahi, *Alo, *Bhi, *Blo;
    const float* bias;
    __nv_bfloat16 *Chi = nullptr, *Clo = nullptr;
    float* Cf = nullptr;
    int K, pid;
    bool outbf;

    if (STAGE == 1) {
        outbf = true;
        if (id < 400) {
            pid = id;       Ahi = g_v_hi; Alo = g_v_lo;
            Bhi = g_Wv_hi;  Blo = g_Wv_lo; K = 2048; bias = bias_v;
            Chi = g_vt_hi;  Clo = g_vt_lo;
        } else if (id < 456) {
            pid = id - 400; Ahi = g_q_hi; Alo = g_q_lo;
            Bhi = g_Wq_hi;  Blo = g_Wq_lo; K = 1024; bias = bias_q;
            Chi = g_qt_hi;  Clo = g_qt_lo;
        } else {
            pid = id - 456; Ahi = g_a_hi; Alo = g_a_lo;
            Bhi = g_Wa_hi;  Blo = g_Wa_lo; K = 1024; bias = bias_a;
            Chi = g_at_hi;  Clo = g_at_lo;
        }
    } else {
        K = 512;
        if (id < 400) {
            pid = id;       Ahi = g_vt_hi; Alo = g_vt_lo;
            Bhi = g_Wvr_hi; Blo = g_Wvr_lo; bias = bias_v;
            Chi = g_v2_hi;  Clo = g_v2_lo; outbf = true;
        } else if (id < 456) {
            pid = id - 400; Ahi = g_qt_hi; Alo = g_qt_lo;
            Bhi = g_Wqr_hi; Blo = g_Wqr_lo; bias = bias_q;
            Cf = g_q2; outbf = false;
        } else {
            pid = id - 456; Ahi = g_at_hi; Alo = g_at_lo;
            Bhi = g_War_hi; Blo = g_War_lo; bias = bias_a;
            Cf = g_a2; outbf = false;
        }
    }
    const int bm = (pid >> 2) * 128;
    const int bn = (pid & 3) * 128;
    const int nchunks = K >> 5;

    auto load_stage = [&](int c) {
        const uint32_t sb = smb + (uint32_t)(c % 3) * STAGE_SZ;
        const int k0 = c << 5;
        #pragma unroll
        for (int i = 0; i < 2; i++) {
            int idx = tid + i * 256;
            int row = idx >> 2;
            int cc  = idx & 3;
            uint32_t so = swz_off(row, cc);
            size_t gA = (size_t)(bm + row) * K + k0 + cc * 8;
            size_t gB = (size_t)(bn + row) * K + k0 + cc * 8;
            cp16(sb + OFF_AH + so, Ahi + gA);
            cp16(sb + OFF_AL + so, Alo + gA);
            cp16(sb + OFF_BH + so, Bhi + gB);
            cp16(sb + OFF_BL + so, Blo + gB);
        }
    };

    float acc[2][8][4];
    #pragma unroll
    for (int mt = 0; mt < 2; mt++)
        #pragma unroll
        for (int nt = 0; nt < 8; nt++)
            #pragma unroll
            for (int i = 0; i < 4; i++) acc[mt][nt][i] = 0.f;

    const int a_r = (lane & 7) | (((lane >> 3) & 1) << 3);
    const int a_c = lane >> 4;
    const int b_r = (lane & 7) | ((lane >> 4) << 3);
    const int b_c = (lane >> 3) & 1;

    load_stage(0);
    cp_commit();
    load_stage(1);
    cp_commit();

    for (int c = 0; c < nchunks; c++) {
        cp_wait<1>();
        __syncthreads();

        if (c + 2 < nchunks) {
            load_stage(c + 2);
            cp_commit();
        } else {
            cp_commit();
        }

        const uint32_t sb = smb + (uint32_t)(c % 3) * STAGE_SZ;

        #pragma unroll
        for (int ks8 = 0; ks8 < 4; ks8 += 2) {
            uint32_t af[2][2][4];
            #pragma unroll
            for (int mt = 0; mt < 2; mt++) {
                int row = wm * 32 + mt * 16 + a_r;
                uint32_t so = swz_off(row, ks8 + a_c);
                ldsm4(af[mt][0], sb + OFF_AH + so);
                ldsm4(af[mt][1], sb + OFF_AL + so);
            }
            uint32_t bf[4][2][4];
            #pragma unroll
            for (int nq = 0; nq < 4; nq++) {
                int row = wn * 64 + nq * 16 + b_r;
                uint32_t so = swz_off(row, ks8 + b_c);
                ldsm4(bf[nq][0], sb + OFF_BH + so);
                ldsm4(bf[nq][1], sb + OFF_BL + so);
            }
            #pragma unroll
            for (int mt = 0; mt < 2; mt++)
                #pragma unroll
                for (int nq = 0; nq < 4; nq++)
                    #pragma unroll
                    for (int h = 0; h < 2; h++)
                        mma_bf16(acc[mt][nq*2+h], af[mt][0], &bf[nq][0][h*2]);
            #pragma unroll
            for (int mt = 0; mt < 2; mt++)
                #pragma unroll
                for (int nq = 0; nq < 4; nq++)
                    #pragma unroll
                    for (int h = 0; h < 2; h++)
                        mma_bf16(acc[mt][nq*2+h], af[mt][0], &bf[nq][1][h*2]);
            #pragma unroll
            for (int mt = 0; mt < 2; mt++)
                #pragma unroll
                for (int nq = 0; nq < 4; nq++)
                    #pragma unroll
                    for (int h = 0; h < 2; h++)
                        mma_bf16(acc[mt][nq*2+h], af[mt][1], &bf[nq][0][h*2]);
        }
    }

    // epilogue: bias + relu
    const int g = lane >> 2;
    const int t = lane & 3;
    #pragma unroll
    for (int mt = 0; mt < 2; mt++) {
        #pragma unroll
        for (int nt = 0; nt < 8; nt++) {
            int row0 = bm + wm * 32 + mt * 16 + g;
            int row1 = row0 + 8;
            int col  = bn + wn * 64 + nt * 8 + t * 2;
            float bs0 = __ldg(bias + col), bs1 = __ldg(bias + col + 1);
            float v00 = fmaxf(acc[mt][nt][0] + bs0, 0.f);
            float v01 = fmaxf(acc[mt][nt][1] + bs1, 0.f);
            float v10 = fmaxf(acc[mt][nt][2] + bs0, 0.f);
            float v11 = fmaxf(acc[mt][nt][3] + bs1, 0.f);
            if (outbf) {
                __nv_bfloat16 h00 = __float2bfloat16(v00);
                __nv_bfloat16 h01 = __float2bfloat16(v01);
                __nv_bfloat16 h10 = __float2bfloat16(v10);
                __nv_bfloat16 h11 = __float2bfloat16(v11);
                __nv_bfloat162 H0 = {h00, h01}, H1 = {h10, h11};
                __nv_bfloat162 L0 = {
                    __float2bfloat16(v00 - __bfloat162float(h00)),
                    __float2bfloat16(v01 - __bfloat162float(h01))};
                __nv_bfloat162 L1 = {
                    __float2bfloat16(v10 - __bfloat162float(h10)),
                    __float2bfloat16(v11 - __bfloat162float(h11))};
                *(__nv_bfloat162*)(Chi + (size_t)row0 * HN + col) = H0;
                *(__nv_bfloat162*)(Clo + (size_t)row0 * HN + col) = L0;
                *(__nv_bfloat162*)(Chi + (size_t)row1 * HN + col) = H1;
                *(__nv_bfloat162*)(Clo + (size_t)row1 * HN + col) = L1;
            } else {
                *(float2*)(Cf + (size_t)row0 * HN + col) = make_float2(v00, v01);
                *(float2*)(Cf + (size_t)row1 * HN + col) = make_float2(v10, v11);
            }
        }
    }
}

// ---------------------------------------------------------------------------
// K7: per (b,n): Tq = Tbar x_j q_,  Tqa = Tq x_k a_ -> TQA_T bf16 hi/lo
// ---------------------------------------------------------------------------
__global__ __launch_bounds__(256)
void tq_tqa_kernel()
{
    extern __shared__ float sm[];
    float* sT  = sm;
    float* sQ  = sm + 8192;
    float* sA  = sm + 8416;
    float* sTq = sm + 8576;

    const int n   = blockIdx.x;
    const int b   = blockIdx.y;
    const int tid = threadIdx.x;

    const float4* Tp = (const float4*)g_Tbar;
    for (int i = tid; i < 2048; i += 256) ((float4*)sT)[i] = Tp[i];

    if (tid < 56) {
        int q  = tid >> 2;
        int j4 = (tid & 3) << 2;
        *(float4*)&sQ[q * 16 + j4] =
            *(const float4*)(g_q2 + (size_t)(b * NQ + q) * 512 + n * 16 + j4);
    }
    if (tid >= 64 && tid < 104) {
        int t  = tid - 64;
        int a  = t >> 2;
        int k4 = (t & 3) << 2;
        *(float4*)&sA[a * 16 + k4] =
            *(const float4*)(g_a2 + (size_t)(b * NA + a) * 512 + n * 16 + k4);
    }
    __syncthreads();

    {
        const int i_ = tid >> 4;
        const int k_ = tid & 15;
        float accx[14], accy[14];
        #pragma unroll
        for (int q = 0; q < 14; q++) { accx[q] = 0.f; accy[q] = 0.f; }
        #pragma unroll
        for (int j = 0; j < 16; j++) {
            float2 t2 = *(const float2*)&sT[(((i_ * 16 + j) * 16) + k_) * 2];
            #pragma unroll
            for (int q = 0; q < 14; q++) {
                float qv = sQ[q * 16 + j];
                accx[q] = fmaf(t2.x, qv, accx[q]);
                accy[q] = fmaf(t2.y, qv, accy[q]);
            }
        }
        #pragma unroll
        for (int q = 0; q < 14; q++)
            *(float2*)&sTq[((q * 16 + i_) * 16 + k_) * 2] =
                make_float2(accx[q], accy[q]);
    }
    __syncthreads();

    float* sOut = sT;
    for (int t = tid; t < 2240; t += 256) {
        int ii  = t / 140;
        int rem = t - ii * 140;
        int q   = rem / 10;
        int a   = rem - q * 10;
        float sx = 0.f, sy = 0.f;
        #pragma unroll
        for (int k = 0; k < 16; k++) {
            float2 tq = *(const float2*)&sTq[((q * 16 + ii) * 16 + k) * 2];
            float  av = sA[a * 16 + k];
            sx = fmaf(tq.x, av, sx);
            sy = fmaf(tq.y, av, sy);
        }
        sOut[ii * 284 + rem * 2]     = sx;
        sOut[ii * 284 + rem * 2 + 1] = sy;
    }
    __syncthreads();

    for (int idx = tid; idx < 560; idx += 256) {
        int c    = idx >> 1;
        int half = idx & 1;
        __nv_bfloat162 H[4], L[4];
        #pragma unroll
        for (int j = 0; j < 4; j++) {
            float v0 = sOut[(half * 8 + j * 2)     * 284 + c];
            float v1 = sOut[(half * 8 + j * 2 + 1) * 284 + c];
            __nv_bfloat16 h0 = __float2bfloat16(v0);
            __nv_bfloat16 h1 = __float2bfloat16(v1);
            H[j] = {h0, h1};
            L[j] = {__float2bfloat16(v0 - __bfloat162float(h0)),
                    __float2bfloat16(v1 - __bfloat162float(h1))};
        }
        size_t off = ((size_t)b * CPAD + c) * 512 + n * 16 + half * 8;
        *(uint4*)(g_tqaT_hi + off) = *(uint4*)H;
        *(uint4*)(g_tqaT_lo + off) = *(uint4*)L;
    }
}

// ---------------------------------------------------------------------------
// K8: out[b][v][c] = sum_k V2[b*100+v][k] * TQA_T[b][c][k]; b = blockIdx.y+b0
// ---------------------------------------------------------------------------
#define K8_STAGE 28672
#define K8_SMEM  (3 * K8_STAGE)
#define K8_BH    16384
#define K8_BL    22528

__global__ __launch_bounds__(256, 2)
void k8_gemm(float* __restrict__ out, int b0)
{
    extern __shared__ char smem[];
    const uint32_t smb = smem_u32(smem);
    const int tid  = threadIdx.x;
    const int wid  = tid >> 5;
    const int lane = tid & 31;
    const int wm   = wid & 3;
    const int wn   = wid >> 2;
    const int bn   = blockIdx.x * 96;
    const int b    = blockIdx.y + b0;

    const __nv_bfloat16* Ahi = g_v2_hi + (size_t)b * 100 * 512;
    const __nv_bfloat16* Alo = g_v2_lo + (size_t)b * 100 * 512;
    const __nv_bfloat16* Bhi = g_tqaT_hi + ((size_t)b * CPAD + bn) * 512;
    const __nv_bfloat16* Blo = g_tqaT_lo + ((size_t)b * CPAD + bn) * 512;

    auto load_stage = [&](int c) {
        const uint32_t sb = smb + (uint32_t)(c % 3) * K8_STAGE;
        const int k0 = c << 5;
        #pragma unroll
        for (int i = 0; i < 2; i++) {
            int idx = tid + i * 256;
            int row = idx >> 2, cc = idx & 3;
            uint32_t so = swz_off(row, cc);
            size_t g = (size_t)row * 512 + k0 + cc * 8;
            cp16(sb + OFF_AH + so, Ahi + g);
            cp16(sb + OFF_AL + so, Alo + g);
        }
        {
            int row = tid >> 2, cc = tid & 3;
            uint32_t so = swz_off(row, cc);
            size_t g = (size_t)row * 512 + k0 + cc * 8;
            cp16(sb + K8_BH + so, Bhi + g);
            cp16(sb + K8_BL + so, Blo + g);
        }
        if (tid < 128) {
            int idx = tid + 256;
            int row = idx >> 2, cc = idx & 3;
            uint32_t so = swz_off(row, cc);
            size_t g = (size_t)row * 512 + k0 + cc * 8;
            cp16(sb + K8_BH + so, Bhi + g);
            cp16(sb + K8_BL + so, Blo + g);
        }
    };

    float acc[2][6][4];
    #pragma unroll
    for (int mt = 0; mt < 2; mt++)
        #pragma unroll
        for (int nt = 0; nt < 6; nt++)
            #pragma unroll
            for (int i = 0; i < 4; i++) acc[mt][nt][i] = 0.f;

    const int a_r = (lane & 7) | (((lane >> 3) & 1) << 3);
    const int a_c = lane >> 4;
    const int b_r = (lane & 7) | ((lane >> 4) << 3);
    const int b_c = (lane >> 3) & 1;

    load_stage(0);
    cp_commit();
    load_stage(1);
    cp_commit();

    for (int c = 0; c < 16; c++) {
        cp_wait<1>();
        __syncthreads();

        if (c + 2 < 16) {
            load_stage(c + 2);
            cp_commit();
        } else {
            cp_commit();
        }

        const uint32_t sb = smb + (uint32_t)(c % 3) * K8_STAGE;

        #pragma unroll
        for (int ks8 = 0; ks8 < 4; ks8 += 2) {
            uint32_t af[2][2][4];
            #pragma unroll
            for (int mt = 0; mt < 2; mt++) {
                int row = wm * 32 + mt * 16 + a_r;
                uint32_t so = swz_off(row, ks8 + a_c);
                ldsm4(af[mt][0], sb + OFF_AH + so);
                ldsm4(af[mt][1], sb + OFF_AL + so);
            }
            uint32_t bf[3][2][4];
            #pragma unroll
            for (int nq = 0; nq < 3; nq++) {
                int row = wn * 48 + nq * 16 + b_r;
                uint32_t so = swz_off(row, ks8 + b_c);
                ldsm4(bf[nq][0], sb + K8_BH + so);
                ldsm4(bf[nq][1], sb + K8_BL + so);
            }
            #pragma unroll
            for (int mt = 0; mt < 2; mt++)
                #pragma unroll
                for (int nq = 0; nq < 3; nq++)
                    #pragma unroll
                    for (int h = 0; h < 2; h++)
                        mma_bf16(acc[mt][nq*2+h], af[mt][0], &bf[nq][0][h*2]);
            #pragma unroll
            for (int mt = 0; mt < 2; mt++)
                #pragma unroll
                for (int nq = 0; nq < 3; nq++)
                    #pragma unroll
                    for (int h = 0; h < 2; h++)
                        mma_bf16(acc[mt][nq*2+h], af[mt][0], &bf[nq][1][h*2]);
            #pragma unroll
            for (int mt = 0; mt < 2; mt++)
                #pragma unroll
                for (int nq = 0; nq < 3; nq++)
                    #pragma unroll
                    for (int h = 0; h < 2; h++)
                        mma_bf16(acc[mt][nq*2+h], af[mt][1], &bf[nq][0][h*2]);
        }
    }

    const int g = lane >> 2;
    const int t = lane & 3;
    #pragma unroll
    for (int mt = 0; mt < 2; mt++) {
        #pragma unroll
        for (int nt = 0; nt < 6; nt++) {
            int v0 = wm * 32 + mt * 16 + g;
            int v1 = v0 + 8;
            int cg = bn + wn * 48 + nt * 8 + t * 2;
            if (cg < QAG) {
                if (v0 < NV)
                    *(float2*)(out + ((size_t)b * NV + v0) * QAG + cg) =
                        make_float2(acc[mt][nt][0], acc[mt][nt][1]);
                if (v1 < NV)
                    *(float2*)(out + ((size_t)b * NV + v1) * QAG + cg) =
                        make_float2(acc[mt][nt][2], acc[mt][nt][3]);
            }
        }
    }
}

// ---------------------------------------------------------------------------
extern "C" void kernel_launch(void* const* d_in, const int* in_sizes, int n_in,
                              void* d_out, int out_size)
{
    const float* v   = (const float*)d_in[0];
    const float* q   = (const float*)d_in[1];
    const float* a   = (const float*)d_in[2];
    const float* Wv  = (const float*)d_in[3];
    const float* bv  = (const float*)d_in[4];
    const float* Wq  = (const float*)d_in[5];
    const float* bq  = (const float*)d_in[6];
    const float* Wa  = (const float*)d_in[7];
    const float* ba  = (const float*)d_in[8];
    const float* Wvr = (const float*)d_in[9];
    const float* bvr = (const float*)d_in[10];
    const float* Wqr = (const float*)d_in[11];
    const float* bqr = (const float*)d_in[12];
    const float* War = (const float*)d_in[13];
    const float* bar = (const float*)d_in[14];
    const float* T   = (const float*)d_in[15];
    float* out       = (float*)d_out;

    cudaFuncSetAttribute(grouped_gemm<1>, cudaFuncAttributeMaxDynamicSharedMemorySize, GEMM_SMEM);
    cudaFuncSetAttribute(grouped_gemm<2>, cudaFuncAttributeMaxDynamicSharedMemorySize, GEMM_SMEM);
    cudaFuncSetAttribute(tq_tqa_kernel, cudaFuncAttributeMaxDynamicSharedMemorySize, 62976);
    cudaFuncSetAttribute(k8_gemm, cudaFuncAttributeMaxDynamicSharedMemorySize, K8_SMEM);

    // streams/events (host objects only; created per call — kernel_launch
    // only runs for correctness + capture)
    cudaStream_t s1, s2, s3;
    cudaStreamCreateWithFlags(&s1, cudaStreamNonBlocking);   // qa chain
    cudaStreamCreateWithFlags(&s2, cudaStreamNonBlocking);   // v half-2 chain
    cudaStreamCreateWithFlags(&s3, cudaStreamNonBlocking);   // weight split
    cudaEvent_t evFork, evW, evH1, evTq, evEnd;
    cudaEventCreateWithFlags(&evFork, cudaEventDisableTiming);
    cudaEventCreateWithFlags(&evW,    cudaEventDisableTiming);
    cudaEventCreateWithFlags(&evH1,   cudaEventDisableTiming);
    cudaEventCreateWithFlags(&evTq,   cudaEventDisableTiming);
    cudaEventCreateWithFlags(&evEnd,  cudaEventDisableTiming);

    // fork all side streams from stream 0
    cudaEventRecord(evFork, 0);
    cudaStreamWaitEvent(s1, evFork, 0);
    cudaStreamWaitEvent(s2, evFork, 0);
    cudaStreamWaitEvent(s3, evFork, 0);

    // s3: weight splits (feeds all GEMMs)
    w_split_kernel<<<(RW_END + 255) / 256, 256, 0, s3>>>(Wv, Wq, Wa, Wvr, Wqr, War);
    cudaEventRecord(evW, s3);

    // s1: qa chain
    qaT_split_kernel<<<(RQ_END + 255) / 256, 256, 0, s1>>>(q, a, T);
    cudaStreamWaitEvent(s1, evW, 0);
    grouped_gemm<1><<<96, 256, GEMM_SMEM, s1>>>(bv, bq, ba, 400);
    grouped_gemm<2><<<96, 256, GEMM_SMEM, s1>>>(bvr, bqr, bar, 400);
    tq_tqa_kernel<<<dim3(RANK, Bb), 256, 62976, s1>>>();
    cudaEventRecord(evTq, s1);

    // stream 0: v half-1 chain
    v_split_kernel<<<(RV_HALF + 255) / 256, 256>>>(v, 0);
    cudaEventRecord(evH1, 0);
    cudaStreamWaitEvent(0, evW, 0);
    grouped_gemm<1><<<200, 256, GEMM_SMEM>>>(bv, bq, ba, 0);      // S1v rows 0..6399
    grouped_gemm<2><<<200, 256, GEMM_SMEM>>>(bvr, bqr, bar, 0);   // S2v rows 0..6399
    cudaStreamWaitEvent(0, evTq, 0);
    k8_gemm<<<dim3(3, 64), 256, K8_SMEM>>>(out, 0);               // b 0..63

    // s2: v half-2 chain (split overlaps S1v-h1)
    cudaStreamWaitEvent(s2, evH1, 0);
    v_split_kernel<<<(RV_HALF + 255) / 256, 256, 0, s2>>>(v, RV_HALF);
    cudaStreamWaitEvent(s2, evW, 0);
    grouped_gemm<1><<<200, 256, GEMM_SMEM, s2>>>(bv, bq, ba, 200);    // rows 6400..12799
    grouped_gemm<2><<<200, 256, GEMM_SMEM, s2>>>(bvr, bqr, bar, 200);
    cudaStreamWaitEvent(s2, evTq, 0);
    k8_gemm<<<dim3(3, 64), 256, K8_SMEM, s2>>>(out, 64);              // b 64..127
    cudaEventRecord(evEnd, s2);

    // join everything back into stream 0
    cudaStreamWaitEvent(0, evEnd, 0);

    cudaEventDestroy(evFork);
    cudaEventDestroy(evW);
    cudaEventDestroy(evH1);
    cudaEventDestroy(evTq);
    cudaEventDestroy(evEnd);
    cudaStreamDestroy(s1);
    cudaStreamDestroy(s2);
    cudaStreamDestroy(s3);
}